// round 13
// baseline (speedup 1.0000x reference)
#include <cuda_runtime.h>

// DifferentiableTTFSEncoder: first-fire one-hot over T=64 steps.
// out[b, t, n] = 1.0f at the first t where the exact-fp32 LIF recurrence
// mem = fmaf(mem, d, c*(1-d)), c = x[b,n]*sens[n], crosses 1.0; else 0.
//
// R13: A/B the driver fill path against the STG write wall (6.08 TB/s,
// R12). Output is sparse (~16% of (b,n) ever fire, one 1.0 each):
//   1) cudaMemsetAsync zeros all 512 MB via the driver's fill engine;
//   2) a small kernel recomputes the bit-exact recurrence per element and
//      scatter-writes only the 1.0s (~330K 4B stores, ~10MB sectors).
// Both ops are graph-capturable and ordered on the default stream.

#define B_DIM 2048
#define N_DIM 1024
#define T_DIM 64
#define NQ    (N_DIM / 4)   // float4 groups per row = 256

__global__ void __launch_bounds__(256)
ttfs_fix_kernel(const float* __restrict__ x,
                const float* __restrict__ sens,
                float* __restrict__ out)
{
    const int gid = blockIdx.x * blockDim.x + threadIdx.x;  // over B*N/4
    const int b  = gid >> 8;        // / NQ
    const int nq = gid & (NQ - 1);  // % NQ

    const float4 xv = reinterpret_cast<const float4*>(x)[gid];
    const float4 sv = reinterpret_cast<const float4*>(sens)[nq];

    const float d   = 0.60653065971263342360f;  // exp(-0.5), fp32-rounded
    const float omd = 1.0f - d;

    const float cc0 = xv.x * sv.x * omd;
    const float cc1 = xv.y * sv.y * omd;
    const float cc2 = xv.z * sv.z * omd;
    const float cc3 = xv.w * sv.w * omd;

    float m0 = 0.0f, m1 = 0.0f, m2 = 0.0f, m3 = 0.0f;
    int tx0 = T_DIM, tx1 = T_DIM, tx2 = T_DIM, tx3 = T_DIM;

    // Bit-exact recurrence; record first crossing step per lane.
    #pragma unroll
    for (int t = 0; t < T_DIM; ++t) {
        m0 = fmaf(m0, d, cc0);
        m1 = fmaf(m1, d, cc1);
        m2 = fmaf(m2, d, cc2);
        m3 = fmaf(m3, d, cc3);
        if (tx0 == T_DIM && m0 >= 1.0f) tx0 = t;
        if (tx1 == T_DIM && m1 >= 1.0f) tx1 = t;
        if (tx2 == T_DIM && m2 >= 1.0f) tx2 = t;
        if (tx3 == T_DIM && m3 >= 1.0f) tx3 = t;
    }

    float* ob = out + (size_t)b * (size_t)(T_DIM * N_DIM) + (size_t)(nq * 4);
    if (tx0 < T_DIM) ob[(size_t)tx0 * N_DIM + 0] = 1.0f;
    if (tx1 < T_DIM) ob[(size_t)tx1 * N_DIM + 1] = 1.0f;
    if (tx2 < T_DIM) ob[(size_t)tx2 * N_DIM + 2] = 1.0f;
    if (tx3 < T_DIM) ob[(size_t)tx3 * N_DIM + 3] = 1.0f;
}

extern "C" void kernel_launch(void* const* d_in, const int* in_sizes, int n_in,
                              void* d_out, int out_size)
{
    const float* x    = (const float*)d_in[0];   // [2048, 1024] f32
    const float* sens = (const float*)d_in[1];   // [1024] f32
    float* out        = (float*)d_out;           // [2048, 64, 1024] f32

    // Phase 1: driver fill engine zeros the whole output (graph-capturable).
    cudaMemsetAsync(out, 0, (size_t)out_size * sizeof(float));

    // Phase 2: sparse fixup — write the ~16% of elements that fire.
    const int total_threads = (B_DIM * N_DIM) / 4;  // 524288
    const int block = 256;
    const int grid  = total_threads / block;        // 2048
    ttfs_fix_kernel<<<grid, block>>>(x, sens, out);
}

// round 14
// speedup vs baseline: 1.3527x; 1.3527x over previous
#include <cuda_runtime.h>

// DifferentiableTTFSEncoder: first-fire one-hot over T=64 steps.
// out[b, t, n] = 1.0f at the first t where the exact-fp32 LIF recurrence
// mem = fmaf(mem, d, c*(1-d)), c = x[b,n]*sens[n], crosses 1.0; else 0.
//
// FINAL KERNEL (R12 config; 79.4us wall, 6.08 TB/s, rel_err 0.0).
// 512 MB write-once output against the GB300 DRAM pure-write wall.
// 13 rounds of measurement established the wall is path-independent:
//  - STG.128/.256, .cs, .wt, bursting, decoupling, and even the driver's
//    cudaMemsetAsync fill engine all saturate at ~6.0-6.1 TB/s;
//  - interleaved one-STG.128.CS-per-step is the optimal drain pattern
//    (any batching/decoupling backs up L1tex and LOWERS DRAM throughput);
//  - occupancy (6-8 blocks/SM), wave shape, and block size are non-levers;
//  - natural register allocation (regs=34) beats forced caps.
// SM side is exonerated (issue=25%, warps parked on store backpressure);
// the kernel runs at ~96% of the demonstrated pure-write ceiling.

#define B_DIM 2048
#define N_DIM 1024
#define T_DIM 64
#define NQ    (N_DIM / 4)   // float4 groups per row = 256

__global__ void __launch_bounds__(256)
ttfs_kernel(const float* __restrict__ x,
            const float* __restrict__ sens,
            float* __restrict__ out)
{
    const int gid = blockIdx.x * blockDim.x + threadIdx.x;  // over B*N/4
    const int b  = gid >> 8;        // / NQ (NQ = 256)
    const int nq = gid & (NQ - 1);  // % NQ

    // Inputs (coalesced float4)
    const float4 xv = reinterpret_cast<const float4*>(x)[gid];
    const float4 sv = reinterpret_cast<const float4*>(sens)[nq];

    const float d   = 0.60653065971263342360f;  // exp(-0.5), fp32-rounded
    const float omd = 1.0f - d;

    // Per-element constant drive c*(1-d)
    const float cc0 = xv.x * sv.x * omd;
    const float cc1 = xv.y * sv.y * omd;
    const float cc2 = xv.z * sv.z * omd;
    const float cc3 = xv.w * sv.w * omd;

    float m0 = 0.0f, m1 = 0.0f, m2 = 0.0f, m3 = 0.0f;
    bool  f0 = false, f1 = false, f2 = false, f3 = false;

    // Output base: out[b, t, n] with n = nq*4; stride per t is N_DIM floats
    float4* op = reinterpret_cast<float4*>(out)
               + (size_t)b * (size_t)T_DIM * NQ + nq;

    #pragma unroll
    for (int t = 0; t < T_DIM; ++t) {
        m0 = fmaf(m0, d, cc0);
        m1 = fmaf(m1, d, cc1);
        m2 = fmaf(m2, d, cc2);
        m3 = fmaf(m3, d, cc3);

        const bool s0 = (m0 >= 1.0f);
        const bool s1 = (m1 >= 1.0f);
        const bool s2 = (m2 >= 1.0f);
        const bool s3 = (m3 >= 1.0f);

        float4 v;
        v.x = (s0 && !f0) ? 1.0f : 0.0f;
        v.y = (s1 && !f1) ? 1.0f : 0.0f;
        v.z = (s2 && !f2) ? 1.0f : 0.0f;
        v.w = (s3 && !f3) ? 1.0f : 0.0f;

        f0 = f0 || s0;
        f1 = f1 || s1;
        f2 = f2 || s2;
        f3 = f3 || s3;

        // Evict-first streaming store (STG.E.128.CS), one per step —
        // the measured-optimal interleaved drain pattern.
        __stcs(op + (size_t)t * NQ, v);
    }
}

extern "C" void kernel_launch(void* const* d_in, const int* in_sizes, int n_in,
                              void* d_out, int out_size)
{
    const float* x    = (const float*)d_in[0];   // [2048, 1024] f32
    const float* sens = (const float*)d_in[1];   // [1024] f32
    float* out        = (float*)d_out;           // [2048, 64, 1024] f32

    const int total_threads = (B_DIM * N_DIM) / 4;  // 524288
    const int block = 256;
    const int grid  = total_threads / block;        // 2048

    ttfs_kernel<<<grid, block>>>(x, sens, out);
}